// round 15
// baseline (speedup 1.0000x reference)
#include <cuda_runtime.h>
#include <cuda_fp16.h>
#include <cstdint>

#define Bn 8
#define Sn 4096
#define Dn 512
#define Hn 8
#define DKn 64
#define DFFn 1024
#define Mn (Bn*Sn)          // 32768 rows
#define NCH 16              // seq chunks for partial KV
#define CHROWS 256
#define EPSA 1e-6f
#define LNEPS 1e-5f
#define D3 (3*Dn)           // 1536

// ---------------- scratch (device globals; no allocation allowed) ----------
__device__ float g_kvp [(size_t)Bn*Hn*NCH*DKn*DKn];
__device__ float g_ksp [(size_t)Bn*Hn*NCH*DKn];
__device__ float g_ks  [(size_t)Bn*Hn*DKn];
__device__ float g_bqkv[D3];

// fp16 buffers
__device__ __half g_qkvh[(size_t)Mn*D3];
__device__ __half g_q2h [(size_t)Mn*Dn];
__device__ __half g_kvhT[(size_t)Bn*Hn*DKn*DKn];
__device__ __half g_xh  [(size_t)Mn*Dn];
__device__ __half g_ath [(size_t)Mn*Dn];
__device__ __half g_yh  [(size_t)Mn*Dn];
__device__ __half g_x1h [(size_t)Mn*Dn];
__device__ __half g_hh  [(size_t)Mn*DFFn];
__device__ __half g_y2h [(size_t)Mn*Dn];
__device__ __half g_wqkvh[(size_t)D3*Dn];
__device__ __half g_woh [Dn*Dn];
__device__ __half g_w1h [DFFn*Dn];
__device__ __half g_w2h [Dn*DFFn];

// ------------------------- PTX helpers -------------------------------------
__device__ __forceinline__ uint32_t smem_u32(const void* p) {
    uint32_t a;
    asm("{ .reg .u64 t; cvta.to.shared.u64 t, %1; cvt.u32.u64 %0, t; }"
        : "=r"(a) : "l"(p));
    return a;
}

__device__ __forceinline__ void ldm4(uint32_t* r, uint32_t addr) {
    asm volatile("ldmatrix.sync.aligned.m8n8.x4.shared.b16 {%0,%1,%2,%3}, [%4];"
                 : "=r"(r[0]), "=r"(r[1]), "=r"(r[2]), "=r"(r[3]) : "r"(addr));
}

__device__ __forceinline__ void ldm4t(uint32_t* r, uint32_t addr) {
    asm volatile("ldmatrix.sync.aligned.m8n8.x4.trans.shared.b16 {%0,%1,%2,%3}, [%4];"
                 : "=r"(r[0]), "=r"(r[1]), "=r"(r[2]), "=r"(r[3]) : "r"(addr));
}

__device__ __forceinline__ void mma16816(float* c, const uint32_t* a,
                                         uint32_t b0, uint32_t b1) {
    asm volatile(
        "mma.sync.aligned.m16n8k16.row.col.f32.f16.f16.f32 "
        "{%0,%1,%2,%3}, {%4,%5,%6,%7}, {%8,%9}, {%0,%1,%2,%3};"
        : "+f"(c[0]), "+f"(c[1]), "+f"(c[2]), "+f"(c[3])
        : "r"(a[0]), "r"(a[1]), "r"(a[2]), "r"(a[3]), "r"(b0), "r"(b1));
}

// ================= HMMA fp16 GEMM: C = A(fp16) @ W(fp16)^T + bias ==========
// EPI: 2 = gelu(x)^2 -> fp16 ; 3 = bias -> fp16 ; 4 = bias + fp16 res -> fp16
// CTA tile 128x128, 256 threads (8 warps, 4M x 2N, warp tile 32x64),
// K-chunk 64, 3 stages, 2 CTAs/SM.
#define PITCH 144
#define ABYTES (128 * PITCH)       // 18432
#define STAGE (2 * ABYTES)         // 36864 (A + W)
#define NSTG 3
#define GSMEM (NSTG * STAGE)       // 110592 -> 2 CTAs/SM

template<int EPI>
__global__ void __launch_bounds__(256, 2) gemm_mma(
    const __half* __restrict__ A, const __half* __restrict__ W,
    const float* __restrict__ bias, const __half* __restrict__ resh,
    __half* __restrict__ Ch, int M, int N, int K)
{
    extern __shared__ char smem[];
    const uint32_t sb = smem_u32(smem);
    const int tid  = threadIdx.x;
    const int bn = blockIdx.x * 128, bm = blockIdx.y * 128;
    const int w = tid >> 5, lane = tid & 31;
    const int wm = w & 3, wn = w >> 2;          // 4M x 2N, warp tile 32x64
    const int mrow = lane >> 3, mr = lane & 7;

    const __half* Ap = A + (size_t)bm * K;
    const __half* Wp = W + (size_t)bn * K;
    const int nch = K >> 6;

    const int lr = tid >> 1, lseg = (tid & 1) * 4;  // row 0..127, 4x16B segs

    auto load_chunk = [&](int kt, int stg) {
        const uint32_t base = sb + stg * STAGE;
        const int off = kt * 64 + lseg * 8;
        const uint32_t dA = base + lr * PITCH + lseg * 16;
        const uint32_t dW = dA + ABYTES;
        const __half* sa = Ap + (size_t)lr * K + off;
        const __half* sw = Wp + (size_t)lr * K + off;
#pragma unroll
        for (int i = 0; i < 4; i++) {
            asm volatile("cp.async.cg.shared.global [%0], [%1], 16;"
                         :: "r"(dA + i * 16), "l"((const void*)(sa + i * 8)));
            asm volatile("cp.async.cg.shared.global [%0], [%1], 16;"
                         :: "r"(dW + i * 16), "l"((const void*)(sw + i * 8)));
        }
        asm volatile("cp.async.commit_group;");
    };

    float acc[2][8][4];
#pragma unroll
    for (int i = 0; i < 2; i++)
#pragma unroll
        for (int j = 0; j < 8; j++)
#pragma unroll
            for (int q = 0; q < 4; q++) acc[i][j][q] = 0.f;

    load_chunk(0, 0);
    load_chunk(1, 1);

    int cs = 0, ls = 2;
    for (int kt = 0; kt < nch; kt++) {
        if (kt == nch - 1) {
            asm volatile("cp.async.wait_group 0;" ::: "memory");
        } else {
            asm volatile("cp.async.wait_group 1;" ::: "memory");
        }
        __syncthreads();
        if (kt + 2 < nch) {
            load_chunk(kt + 2, ls);
            ls = (ls == 2) ? 0 : ls + 1;
        }

        const uint32_t base = sb + cs * STAGE;
        cs = (cs == 2) ? 0 : cs + 1;
#pragma unroll
        for (int ks = 0; ks < 4; ks++) {
            uint32_t ah[2][4];
#pragma unroll
            for (int i = 0; i < 2; i++) {
                const int rowA = wm * 32 + i * 16 + (mrow & 1) * 8 + mr;
                const uint32_t cA = ks * 32 + (mrow >> 1) * 16;
                ldm4(ah[i], base + rowA * PITCH + cA);
            }
#pragma unroll
            for (int jp = 0; jp < 4; jp++) {
                const int rowB = wn * 64 + jp * 16 + (mrow >> 1) * 8 + mr;
                const uint32_t cB = ks * 32 + (mrow & 1) * 16;
                uint32_t t0[4];
                ldm4(t0, base + ABYTES + rowB * PITCH + cB);
#pragma unroll
                for (int i = 0; i < 2; i++) {
                    mma16816(acc[i][2*jp],     ah[i], t0[0], t0[1]);
                    mma16816(acc[i][2*jp + 1], ah[i], t0[2], t0[3]);
                }
            }
        }
    }
    __syncthreads();

    const int tg = lane >> 2, ti = lane & 3;
#pragma unroll
    for (int i = 0; i < 2; i++) {
#pragma unroll
        for (int j = 0; j < 8; j++) {
            const int gr0 = bm + wm * 32 + i * 16 + tg;
            const int gc  = bn + wn * 64 + j * 8 + ti * 2;
            const float b0 = bias[gc], b1 = bias[gc + 1];
#pragma unroll
            for (int hfl = 0; hfl < 2; hfl++) {
                const int gr = gr0 + hfl * 8;
                float v0 = acc[i][j][2*hfl + 0] + b0;
                float v1 = acc[i][j][2*hfl + 1] + b1;
                const size_t off = (size_t)gr * N + gc;
                if (EPI == 4) {
                    float2 rv = __half22float2(*(const __half2*)(resh + off));
                    v0 += rv.x; v1 += rv.y;
                }
                if (EPI == 2) {
                    float g0 = 0.5f * v0 * (1.0f + erff(v0 * 0.7071067811865476f));
                    float g1 = 0.5f * v1 * (1.0f + erff(v1 * 0.7071067811865476f));
                    v0 = g0 * g0; v1 = g1 * g1;
                }
                *(__half2*)(Ch + off) = __floats2half2_rn(v0, v1);
            }
        }
    }
}

// ------------------ fp32 -> fp16 convert (x) --------------------------------
__global__ void cvt_h(const float* __restrict__ in, __half* __restrict__ out, int n4)
{
    const int i = blockIdx.x * 256 + threadIdx.x;
    if (i >= n4) return;
    float4 v = ((const float4*)in)[i];
    ((__half2*)out)[2 * i]     = __floats2half2_rn(v.x, v.y);
    ((__half2*)out)[2 * i + 1] = __floats2half2_rn(v.z, v.w);
}

// --------- all 6 weight converts in one launch (flat float4 index) ----------
__global__ void cvt_weights(const float* __restrict__ wq, const float* __restrict__ wk,
                            const float* __restrict__ wv, const float* __restrict__ wo,
                            const float* __restrict__ w1, const float* __restrict__ w2,
                            __half* __restrict__ wqkvh, __half* __restrict__ woh,
                            __half* __restrict__ w1h, __half* __restrict__ w2h)
{
    const int i = blockIdx.x * 256 + threadIdx.x;   // float4 index, < 524288
    const float* src;
    __half* dst;
    int li;
    if (i < 196608) {
        li = i & 65535;
        src = (i < 65536) ? wq : (i < 131072) ? wk : wv;
        dst = wqkvh + (size_t)(i >> 16) * (Dn * Dn);
    } else if (i < 262144) { li = i - 196608; src = wo; dst = woh; }
    else if (i < 393216)   { li = i - 262144; src = w1; dst = w1h; }
    else                   { li = i - 393216; src = w2; dst = w2h; }
    float4 v = ((const float4*)src)[li];
    ((__half2*)dst)[2 * li]     = __floats2half2_rn(v.x, v.y);
    ((__half2*)dst)[2 * li + 1] = __floats2half2_rn(v.z, v.w);
}

// ------------------ pack 3 bias vectors into one ----------------------------
__global__ void pack3(const float* __restrict__ a, const float* __restrict__ b,
                      const float* __restrict__ c, float* __restrict__ o)
{
    const int i = blockIdx.x * 256 + threadIdx.x;
    if (i < Dn)            o[i] = a[i];
    else if (i < 2 * Dn)   o[i] = b[i - Dn];
    else if (i < 3 * Dn)   o[i] = c[i - 2 * Dn];
}

// ------------- conv(q,k,v) + elu+1(q,k) + partial KV (HMMA) / Ksum ---------
#define CPITCH 144
__global__ __launch_bounds__(256) void conv_pre(
    const __half* __restrict__ qkv,
    const float* __restrict__ qcw, const float* __restrict__ qcb,
    const float* __restrict__ kcw, const float* __restrict__ kcb,
    const float* __restrict__ vcw, const float* __restrict__ vcb)
{
    const int c = blockIdx.x, h = blockIdx.y, b = blockIdx.z;
    const int t  = threadIdx.x;
    const int p  = t & 31;
    const int rl = t >> 5;
    const int ch = 2 * p;
    const int w = t >> 5, lane = t & 31;
    const int mrow = lane >> 3, mr = lane & 7;
    const int dbase = (w & 3) * 16, ebase = (w >> 2) * 32;

    __shared__ __align__(16) char k2s[64 * CPITCH];
    __shared__ __align__(16) char v2s[64 * CPITCH];
    const uint32_t kbse = smem_u32(k2s);
    const uint32_t vbse = smem_u32(v2s);

    const float qw0a = qcw[ch*3+0], qw1a = qcw[ch*3+1], qw2a = qcw[ch*3+2], qba = qcb[ch];
    const float qw0b = qcw[ch*3+3], qw1b = qcw[ch*3+4], qw2b = qcw[ch*3+5], qbb = qcb[ch+1];
    const float kw0a = kcw[ch*3+0], kw1a = kcw[ch*3+1], kw2a = kcw[ch*3+2], kba = kcb[ch];
    const float kw0b = kcw[ch*3+3], kw1b = kcw[ch*3+4], kw2b = kcw[ch*3+5], kbb = kcb[ch+1];
    const float vw0a = vcw[ch*3+0], vw1a = vcw[ch*3+1], vw2a = vcw[ch*3+2], vba = vcb[ch];
    const float vw0b = vcw[ch*3+3], vw1b = vcw[ch*3+4], vw2b = vcw[ch*3+5], vbb = vcb[ch+1];

    float accm[4][4];
#pragma unroll
    for (int i = 0; i < 4; i++)
#pragma unroll
        for (int j = 0; j < 4; j++) accm[i][j] = 0.f;
    float ksacc = 0.f;

    for (int sub = 0; sub < 4; sub++) {
        __syncthreads();
        const int s0 = c * CHROWS + sub * 64 + rl * 8;
        const size_t qb0  = ((size_t)(b * Sn + s0)) * D3 + h * DKn + ch;
        const size_t q2b0 = ((size_t)(b * Sn + s0)) * Dn + h * DKn + ch;
        float2 qm1 = {0.f,0.f}, qm2 = {0.f,0.f};
        float2 km1 = {0.f,0.f}, km2 = {0.f,0.f};
        float2 vm1 = {0.f,0.f}, vm2 = {0.f,0.f};
        if (s0 >= 1) {
            qm1 = __half22float2(*(const __half2*)(qkv + qb0 - D3));
            km1 = __half22float2(*(const __half2*)(qkv + qb0 - D3 + Dn));
            vm1 = __half22float2(*(const __half2*)(qkv + qb0 - D3 + 2 * Dn));
        }
        if (s0 >= 2) {
            qm2 = __half22float2(*(const __half2*)(qkv + qb0 - 2 * D3));
            km2 = __half22float2(*(const __half2*)(qkv + qb0 - 2 * D3 + Dn));
            vm2 = __half22float2(*(const __half2*)(qkv + qb0 - 2 * D3 + 2 * Dn));
        }
#pragma unroll
        for (int i = 0; i < 8; i++) {
            const int r = rl * 8 + i;
            const size_t base = qb0 + (size_t)i * D3;

            float2 q0 = __half22float2(*(const __half2*)(qkv + base));
            float qcx = qw0a*qm2.x + qw1a*qm1.x + qw2a*q0.x + qba;
            float qcy = qw0b*qm2.y + qw1b*qm1.y + qw2b*q0.y + qbb;
            qcx = qcx > 0.f ? qcx + 1.f : __expf(qcx);
            qcy = qcy > 0.f ? qcy + 1.f : __expf(qcy);
            *(__half2*)(g_q2h + q2b0 + (size_t)i * Dn) = __floats2half2_rn(qcx, qcy);
            qm2 = qm1; qm1 = q0;

            float2 k0 = __half22float2(*(const __half2*)(qkv + base + Dn));
            float kcx = kw0a*km2.x + kw1a*km1.x + kw2a*k0.x + kba;
            float kcy = kw0b*km2.y + kw1b*km1.y + kw2b*k0.y + kbb;
            kcx = kcx > 0.f ? kcx + 1.f : __expf(kcx);
            kcy = kcy > 0.f ? kcy + 1.f : __expf(kcy);
            *(__half2*)(k2s + r * CPITCH + ch * 2) = __floats2half2_rn(kcx, kcy);
            km2 = km1; km1 = k0;

            float2 v0 = __half22float2(*(const __half2*)(qkv + base + 2 * Dn));
            float vcx = vw0a*vm2.x + vw1a*vm1.x + vw2a*v0.x + vba;
            float vcy = vw0b*vm2.y + vw1b*vm1.y + vw2b*v0.y + vbb;
            *(__half2*)(v2s + r * CPITCH + ch * 2) = __floats2half2_rn(vcx, vcy);
            vm2 = vm1; vm1 = v0;
        }
        __syncthreads();
        if (t < 64) {
#pragma unroll 8
            for (int r = 0; r < 64; r++)
                ksacc += __half2float(*(const __half*)(k2s + r * CPITCH + t * 2));
        }
#pragma unroll
        for (int ksb = 0; ksb < 4; ksb++) {
            uint32_t a[4];
            ldm4t(a, kbse + (ksb * 16 + (mrow >> 1) * 8 + mr) * CPITCH
                      + dbase * 2 + (mrow & 1) * 16);
#pragma unroll
            for (int jb = 0; jb < 2; jb++) {
                uint32_t t4[4];
                ldm4t(t4, vbse + (ksb * 16 + (mrow & 1) * 8 + mr) * CPITCH
                          + (ebase + jb * 16) * 2 + (mrow >> 1) * 16);
                mma16816(accm[2*jb],     a, t4[0], t4[1]);
                mma16816(accm[2*jb + 1], a, t4[2], t4[3]);
            }
        }
    }

    const int bh = b * Hn + h;
    const size_t kvbase = ((size_t)bh * NCH + c) * (DKn * DKn);
    const int tg = lane >> 2, ti = lane & 3;
#pragma unroll
    for (int jn = 0; jn < 4; jn++) {
#pragma unroll
        for (int hfl = 0; hfl < 2; hfl++) {
            const int d = dbase + hfl * 8 + tg;
            const int e = ebase + jn * 8 + ti * 2;
            g_kvp[kvbase + (size_t)d * DKn + e]     = accm[jn][2*hfl];
            g_kvp[kvbase + (size_t)d * DKn + e + 1] = accm[jn][2*hfl + 1];
        }
    }
    if (t < 64)
        g_ksp[((size_t)bh * NCH + c) * DKn + t] = ksacc;
}

// ---- reduce partial KV (-> fp16 transposed) / Ksum; grid (64, 4) ----------
__global__ void kv_reduce()
{
    const int bh = blockIdx.x, q = blockIdx.y, t = threadIdx.x;
    const int idx = q * 1024 + t * 4;
#pragma unroll
    for (int u = 0; u < 4; u++) {
        const int id = idx + u;
        float s = 0.f;
#pragma unroll
        for (int c = 0; c < NCH; c++)
            s += g_kvp[((size_t)bh * NCH + c) * (DKn * DKn) + id];
        const int d = id >> 6, e = id & 63;
        g_kvhT[(size_t)bh * (DKn * DKn) + e * DKn + d] = __float2half_rn(s);
    }
    if (q == 0 && t < DKn) {
        float s = 0.f;
#pragma unroll
        for (int c = 0; c < NCH; c++)
            s += g_ksp[((size_t)bh * NCH + c) * DKn + t];
        g_ks[(size_t)bh * DKn + t] = s;
    }
}

// ---- attn apply via HMMA: Vn = (Q @ KV) / (Q.(Ksum+eps)); 128 rows/block --
#define APITCH 144
__global__ __launch_bounds__(128) void attn_apply()
{
    const int st = blockIdx.x, h = blockIdx.y, b = blockIdx.z;
    const int t = threadIdx.x;
    const int bh = b * Hn + h;
    const int w = t >> 5, lane = t & 31;
    const int mrow = lane >> 3, mr = lane & 7;

    __shared__ __align__(16) char qsmem[64 * APITCH];
    __shared__ __align__(16) char ksmem[64 * APITCH];
    __shared__ float kss[64];
    __shared__ float zinv[64];

    const uint32_t qb = smem_u32(qsmem);
    const uint32_t kb = smem_u32(ksmem);

    for (int idx = t; idx < 1024; idx += 128) {
        const int r = idx >> 4, c4 = idx & 15;
        *(uint2*)(ksmem + r * APITCH + c4 * 8) =
            *(const uint2*)(g_kvhT + (size_t)bh * (DKn * DKn) + r * DKn + c4 * 4);
    }
    if (t < DKn) kss[t] = g_ks[(size_t)bh * DKn + t] + EPSA;

    for (int tile = 0; tile < 2; tile++) {
        const int row0 = st * 128 + tile * 64;
        __syncthreads();
        for (int idx = t; idx < 1024; idx += 128) {
            const int r = idx >> 4, c4 = idx & 15;
            *(uint2*)(qsmem + r * APITCH + c4 * 8) =
                *(const uint2*)(g_q2h + ((size_t)(b * Sn + row0 + r)) * Dn
                                + h * DKn + c4 * 4);
        }
        __syncthreads();

        {
            const int s = t >> 1, part = t & 1;
            float z = 0.f;
            const __half2* rp = (const __half2*)(qsmem + s * APITCH + part * 64);
#pragma unroll
            for (int d = 0; d < 16; d++) {
                float2 qv = __half22float2(rp[d]);
                z += qv.x * kss[part * 32 + 2 * d] + qv.y * kss[part * 32 + 2 * d + 1];
            }
            z += __shfl_xor_sync(0xffffffffu, z, 1);
            if (part == 0) zinv[s] = 1.0f / z;
        }

        float acc[8][4];
#pragma unroll
        for (int j = 0; j < 8; j++)
#pragma unroll
            for (int q = 0; q < 4; q++) acc[j][q] = 0.f;

#pragma unroll
        for (int ks = 0; ks < 4; ks++) {
            uint32_t ah[4];
            const int rowA = w * 16 + (mrow & 1) * 8 + mr;
            ldm4(ah, qb + rowA * APITCH + ks * 32 + (mrow >> 1) * 16);
#pragma unroll
            for (int jp = 0; jp < 4; jp++) {
                const int rowB = jp * 16 + (mrow >> 1) * 8 + mr;
                uint32_t t0[4];
                ldm4(t0, kb + rowB * APITCH + ks * 32 + (mrow & 1) * 16);
                mma16816(acc[2*jp],     ah, t0[0], t0[1]);
                mma16816(acc[2*jp + 1], ah, t0[2], t0[3]);
            }
        }
        __syncthreads();

        const int tg = lane >> 2, ti = lane & 3;
#pragma unroll
        for (int j = 0; j < 8; j++) {
            const int col = j * 8 + ti * 2;
#pragma unroll
            for (int hfl = 0; hfl < 2; hfl++) {
                const int row = w * 16 + hfl * 8 + tg;
                const float zi = zinv[row];
                const size_t off = ((size_t)(b * Sn + row0 + row)) * Dn
                                   + h * DKn + col;
                *(__half2*)(g_ath + off) =
                    __floats2half2_rn(zi * acc[j][2*hfl], zi * acc[j][2*hfl + 1]);
            }
        }
    }
}

// -------------------- LayerNorm (D=512), warp per row, fp16 in -------------
template<bool OUTF32>
__global__ __launch_bounds__(256) void ln_kernel(
    const __half* __restrict__ in, const float* __restrict__ gw,
    const float* __restrict__ bw, float* __restrict__ out,
    __half* __restrict__ oh)
{
    const int warp = threadIdx.x >> 5, lane = threadIdx.x & 31;
    const int row = blockIdx.x * 8 + warp;
    const uint4* rp = (const uint4*)(in + (size_t)row * Dn);

    float vals[16];
    float s1 = 0.f, s2 = 0.f;
#pragma unroll
    for (int i = 0; i < 2; i++) {
        uint4 raw = rp[lane + i * 32];
        const uint32_t u[4] = {raw.x, raw.y, raw.z, raw.w};
#pragma unroll
        for (int k = 0; k < 4; k++) {
            float2 f = __half22float2(*(const __half2*)&u[k]);
            vals[i * 8 + 2 * k]     = f.x;
            vals[i * 8 + 2 * k + 1] = f.y;
            s1 += f.x + f.y;
            s2 += f.x * f.x + f.y * f.y;
        }
    }
#pragma unroll
    for (int o = 16; o > 0; o >>= 1) {
        s1 += __shfl_xor_sync(0xffffffffu, s1, o);
        s2 += __shfl_xor_sync(0xffffffffu, s2, o);
    }
    const float m = s1 * (1.0f / Dn);
    const float rr = rsqrtf(s2 * (1.0f / Dn) - m * m + LNEPS);

#pragma unroll
    for (int i = 0; i < 2; i++) {
        const int c0 = (lane + i * 32) * 8;
        float o8[8];
#pragma unroll
        for (int k = 0; k < 2; k++) {
            const float4 g4 = *(const float4*)(gw + c0 + k * 4);
            const float4 b4 = *(const float4*)(bw + c0 + k * 4);
            o8[k*4+0] = (vals[i*8 + k*4 + 0] - m) * rr * g4.x + b4.x;
            o8[k*4+1] = (vals[i*8 + k*4 + 1] - m) * rr * g4.y + b4.y;
            o8[k*4+2] = (vals[i*8 + k*4 + 2] - m) * rr * g4.z + b4.z;
            o8[k*4+3] = (vals[i*8 + k*4 + 3] - m) * rr * g4.w + b4.w;
        }
        if (OUTF32) {
#pragma unroll
            for (int k = 0; k < 2; k++) {
                float4 o4; o4.x = o8[k*4]; o4.y = o8[k*4+1];
                o4.z = o8[k*4+2]; o4.w = o8[k*4+3];
                *(float4*)(out + (size_t)row * Dn + c0 + k * 4) = o4;
            }
        } else {
            uint4 packed;
            __half2 p0 = __floats2half2_rn(o8[0], o8[1]);
            __half2 p1 = __floats2half2_rn(o8[2], o8[3]);
            __half2 p2 = __floats2half2_rn(o8[4], o8[5]);
            __half2 p3 = __floats2half2_rn(o8[6], o8[7]);
            packed.x = *(uint32_t*)&p0; packed.y = *(uint32_t*)&p1;
            packed.z = *(uint32_t*)&p2; packed.w = *(uint32_t*)&p3;
            *(uint4*)(oh + (size_t)row * Dn + c0) = packed;
        }
    }
}

// ------------------------------- launch ------------------------------------
extern "C" void kernel_launch(void* const* d_in, const int* in_sizes, int n_in,
                              void* d_out, int out_size)
{
    const float* x    = (const float*)d_in[0];
    const float* wq   = (const float*)d_in[1];
    const float* bq   = (const float*)d_in[2];
    const float* wk   = (const float*)d_in[3];
    const float* bk   = (const float*)d_in[4];
    const float* wv   = (const float*)d_in[5];
    const float* bv   = (const float*)d_in[6];
    const float* wo   = (const float*)d_in[7];
    const float* bo   = (const float*)d_in[8];
    const float* qcw  = (const float*)d_in[9];
    const float* qcb  = (const float*)d_in[10];
    const float* kcw  = (const float*)d_in[11];
    const float* kcb  = (const float*)d_in[12];
    const float* vcw  = (const float*)d_in[13];
    const float* vcb  = (const float*)d_in[14];
    const float* w1   = (const float*)d_in[15];
    const float* b1   = (const float*)d_in[16];
    const float* w2   = (const float*)d_in[17];
    const float* b2   = (const float*)d_in[18];
    const float* ln1g = (const float*)d_in[19];
    const float* ln1b = (const float*)d_in[20];
    const float* ln2g = (const float*)d_in[21];
    const float* ln2b = (const float*)d_in[22];
    float* out = (float*)d_out;

    float* pbqkv;
    cudaGetSymbolAddress((void**)&pbqkv, g_bqkv);

    __half *pqkvh, *pxh, *path, *pyh, *px1h, *phh, *py2h;
    __half *pwqkvh, *pwoh, *pw1h, *pw2h;
    cudaGetSymbolAddress((void**)&pqkvh,  g_qkvh);
    cudaGetSymbolAddress((void**)&pxh,    g_xh);
    cudaGetSymbolAddress((void**)&path,   g_ath);
    cudaGetSymbolAddress((void**)&pyh,    g_yh);
    cudaGetSymbolAddress((void**)&px1h,   g_x1h);
    cudaGetSymbolAddress((void**)&phh,    g_hh);
    cudaGetSymbolAddress((void**)&py2h,   g_y2h);
    cudaGetSymbolAddress((void**)&pwqkvh, g_wqkvh);
    cudaGetSymbolAddress((void**)&pwoh,   g_woh);
    cudaGetSymbolAddress((void**)&pw1h,   g_w1h);
    cudaGetSymbolAddress((void**)&pw2h,   g_w2h);

    cudaFuncSetAttribute(gemm_mma<2>, cudaFuncAttributeMaxDynamicSharedMemorySize, GSMEM);
    cudaFuncSetAttribute(gemm_mma<3>, cudaFuncAttributeMaxDynamicSharedMemorySize, GSMEM);
    cudaFuncSetAttribute(gemm_mma<4>, cudaFuncAttributeMaxDynamicSharedMemorySize, GSMEM);

    const dim3 gridQKV(D3 / 128, Mn / 128);   // (12, 256)
    const dim3 gridD(Dn / 128, Mn / 128);     // (4, 256)
    const dim3 gridF(DFFn / 128, Mn / 128);   // (8, 256)

    // elementwise prep
    cvt_h<<<(Mn * Dn / 4 + 255) / 256, 256>>>(x, pxh, Mn * Dn / 4);
    cvt_weights<<<2048, 256>>>(wq, wk, wv, wo, w1, w2,
                               pwqkvh, pwoh, pw1h, pw2h);
    pack3<<<(D3 + 255) / 256, 256>>>(bq, bk, bv, pbqkv);

    // merged QKV projection -> fp16
    gemm_mma<3><<<gridQKV, 256, GSMEM>>>(pxh, pwqkvh, pbqkv, nullptr,
                                         pqkvh, Mn, D3, Dn);

    // depthwise conv + elu+1 + partial KV (HMMA) / Ksum
    conv_pre<<<dim3(NCH, Hn, Bn), 256>>>(pqkvh, qcw, qcb, kcw, kcb, vcw, vcb);
    kv_reduce<<<dim3(Bn * Hn, 4), 256>>>();
    attn_apply<<<dim3(Sn / 128, Hn, Bn), 128>>>();

    // O-proj + residual(xh fp16) -> fp16 y; LN1 fp16->fp16
    gemm_mma<4><<<gridD, 256, GSMEM>>>(path, pwoh, bo, pxh, pyh, Mn, Dn, Dn);
    ln_kernel<false><<<Mn / 8, 256>>>(pyh, ln1g, ln1b, nullptr, px1h);

    // FFN1 gelu^2 -> fp16; FFN2 + residual(x1h fp16) -> fp16; LN2 -> fp32 out
    gemm_mma<2><<<gridF, 256, GSMEM>>>(px1h, pw1h, b1, nullptr, phh, Mn, DFFn, Dn);
    gemm_mma<4><<<gridD, 256, GSMEM>>>(phh, pw2h, b2, px1h, py2h, Mn, Dn, DFFn);
    ln_kernel<true><<<Mn / 8, 256>>>(py2h, ln2g, ln2b, out, nullptr);
}

// round 16
// speedup vs baseline: 1.1424x; 1.1424x over previous
#include <cuda_runtime.h>
#include <cuda_fp16.h>
#include <cstdint>

#define Bn 8
#define Sn 4096
#define Dn 512
#define Hn 8
#define DKn 64
#define DFFn 1024
#define Mn (Bn*Sn)          // 32768 rows
#define NCH 16              // seq chunks for partial KV
#define CHROWS 256
#define EPSA 1e-6f
#define LNEPS 1e-5f
#define D3 (3*Dn)           // 1536

// ---------------- scratch (device globals; no allocation allowed) ----------
__device__ float g_kvp [(size_t)Bn*Hn*NCH*DKn*DKn];
__device__ float g_ksp [(size_t)Bn*Hn*NCH*DKn];
__device__ float g_ks  [(size_t)Bn*Hn*DKn];
__device__ float g_bqkv[D3];

// fp16 buffers
__device__ __half g_qkvh[(size_t)Mn*D3];
__device__ __half g_q2h [(size_t)Mn*Dn];
__device__ __half g_kvhT[(size_t)Bn*Hn*DKn*DKn];
__device__ __half g_xh  [(size_t)Mn*Dn];
__device__ __half g_ath [(size_t)Mn*Dn];
__device__ __half g_yh  [(size_t)Mn*Dn];
__device__ __half g_x1h [(size_t)Mn*Dn];
__device__ __half g_hh  [(size_t)Mn*DFFn];
__device__ __half g_y2h [(size_t)Mn*Dn];
__device__ __half g_wqkvh[(size_t)D3*Dn];
__device__ __half g_woh [Dn*Dn];
__device__ __half g_w1h [DFFn*Dn];
__device__ __half g_w2h [Dn*DFFn];

// ------------------------- PTX helpers -------------------------------------
__device__ __forceinline__ uint32_t smem_u32(const void* p) {
    uint32_t a;
    asm("{ .reg .u64 t; cvta.to.shared.u64 t, %1; cvt.u32.u64 %0, t; }"
        : "=r"(a) : "l"(p));
    return a;
}

__device__ __forceinline__ void ldm4(uint32_t* r, uint32_t addr) {
    asm volatile("ldmatrix.sync.aligned.m8n8.x4.shared.b16 {%0,%1,%2,%3}, [%4];"
                 : "=r"(r[0]), "=r"(r[1]), "=r"(r[2]), "=r"(r[3]) : "r"(addr));
}

__device__ __forceinline__ void ldm4t(uint32_t* r, uint32_t addr) {
    asm volatile("ldmatrix.sync.aligned.m8n8.x4.trans.shared.b16 {%0,%1,%2,%3}, [%4];"
                 : "=r"(r[0]), "=r"(r[1]), "=r"(r[2]), "=r"(r[3]) : "r"(addr));
}

__device__ __forceinline__ void mma16816(float* c, const uint32_t* a,
                                         uint32_t b0, uint32_t b1) {
    asm volatile(
        "mma.sync.aligned.m16n8k16.row.col.f32.f16.f16.f32 "
        "{%0,%1,%2,%3}, {%4,%5,%6,%7}, {%8,%9}, {%0,%1,%2,%3};"
        : "+f"(c[0]), "+f"(c[1]), "+f"(c[2]), "+f"(c[3])
        : "r"(a[0]), "r"(a[1]), "r"(a[2]), "r"(a[3]), "r"(b0), "r"(b1));
}

// ================= HMMA fp16 GEMM: C = A(fp16) @ W(fp16)^T + bias ==========
// EPI: 2 = gelu(x)^2 -> fp16 ; 3 = bias -> fp16 ; 4 = bias + fp16 res -> fp16
// CTA 128x256, 512 thr (16 warps, 4M x 4N, warp tile 32x64), K-chunk 64,
// 3 stages; A-fragments double-buffered across ks, B across jp.
#define PITCH 144
#define ABYTES (128 * PITCH)       // 18432
#define WBYTES (256 * PITCH)       // 36864
#define STAGE (ABYTES + WBYTES)    // 55296
#define NSTG 3
#define GSMEM (NSTG * STAGE)       // 165888

template<int EPI>
__global__ void __launch_bounds__(512) gemm_mma(
    const __half* __restrict__ A, const __half* __restrict__ W,
    const float* __restrict__ bias, const __half* __restrict__ resh,
    __half* __restrict__ Ch, int M, int N, int K)
{
    extern __shared__ char smem[];
    const uint32_t sb = smem_u32(smem);
    const int tid  = threadIdx.x;
    const int bn = blockIdx.x * 256, bm = blockIdx.y * 128;
    const int w = tid >> 5, lane = tid & 31;
    const int wm = w & 3, wn = w >> 2;
    const int mrow = lane >> 3, mr = lane & 7;

    const __half* Ap = A + (size_t)bm * K;
    const __half* Wp = W + (size_t)bn * K;
    const int nch = K >> 6;

    const int lr8 = tid >> 3, lc8 = tid & 7;

    auto load_chunk = [&](int kt, int stg) {
        const uint32_t base = sb + stg * STAGE;
        const int off = kt * 64 + lc8 * 8;
        const uint32_t dA = base + lr8 * PITCH + lc8 * 16;
        asm volatile("cp.async.cg.shared.global [%0], [%1], 16;"
                     :: "r"(dA), "l"((const void*)(Ap + (size_t)lr8 * K + off)));
        asm volatile("cp.async.cg.shared.global [%0], [%1], 16;"
                     :: "r"(dA + 64 * PITCH),
                        "l"((const void*)(Ap + (size_t)(lr8 + 64) * K + off)));
        const uint32_t dW = base + ABYTES + lr8 * PITCH + lc8 * 16;
#pragma unroll
        for (int i = 0; i < 4; i++) {
            asm volatile("cp.async.cg.shared.global [%0], [%1], 16;"
                         :: "r"(dW + i * 64 * PITCH),
                            "l"((const void*)(Wp + (size_t)(lr8 + i * 64) * K + off)));
        }
        asm volatile("cp.async.commit_group;");
    };

    // fragment address helpers
    const int rowA0 = wm * 32 + (mrow & 1) * 8 + mr;           // +16 for i=1
    const uint32_t cAo = (mrow >> 1) * 16;
    const int rowB0 = wn * 64 + (mrow >> 1) * 8 + mr;          // + jp*16
    const uint32_t cBo = (mrow & 1) * 16;

    float acc[2][8][4];
#pragma unroll
    for (int i = 0; i < 2; i++)
#pragma unroll
        for (int j = 0; j < 8; j++)
#pragma unroll
            for (int q = 0; q < 4; q++) acc[i][j][q] = 0.f;

    load_chunk(0, 0);
    load_chunk(1, 1);

    int cs = 0, ls = 2;
    for (int kt = 0; kt < nch; kt++) {
        if (kt == nch - 1) {
            asm volatile("cp.async.wait_group 0;" ::: "memory");
        } else {
            asm volatile("cp.async.wait_group 1;" ::: "memory");
        }
        __syncthreads();
        if (kt + 2 < nch) {
            load_chunk(kt + 2, ls);
            ls = (ls == 2) ? 0 : ls + 1;
        }

        const uint32_t base = sb + cs * STAGE;
        cs = (cs == 2) ? 0 : cs + 1;

        uint32_t ah[2][2][4];   // [buf][i][frag]
        uint32_t bf[2][4];      // [buf][frag]
        // prime: A frags for ks=0, B frag for (ks=0, jp=0)
        ldm4(ah[0][0], base + rowA0 * PITCH + cAo);
        ldm4(ah[0][1], base + (rowA0 + 16) * PITCH + cAo);
        ldm4(bf[0], base + ABYTES + rowB0 * PITCH + cBo);

#pragma unroll
        for (int ks = 0; ks < 4; ks++) {
            const int ab = ks & 1;
            if (ks < 3) {   // prefetch next ks's A fragments
                const uint32_t cA = (ks + 1) * 32 + cAo;
                ldm4(ah[ab ^ 1][0], base + rowA0 * PITCH + cA);
                ldm4(ah[ab ^ 1][1], base + (rowA0 + 16) * PITCH + cA);
            }
#pragma unroll
            for (int jp = 0; jp < 4; jp++) {
                const int bb = jp & 1;
                // prefetch next B fragment (next jp, or next ks's jp=0)
                if (jp < 3) {
                    ldm4(bf[bb ^ 1], base + ABYTES
                         + (rowB0 + (jp + 1) * 16) * PITCH + ks * 32 + cBo);
                } else if (ks < 3) {
                    ldm4(bf[bb ^ 1], base + ABYTES
                         + rowB0 * PITCH + (ks + 1) * 32 + cBo);
                }
#pragma unroll
                for (int i = 0; i < 2; i++) {
                    mma16816(acc[i][2*jp],     ah[ab][i], bf[bb][0], bf[bb][1]);
                    mma16816(acc[i][2*jp + 1], ah[ab][i], bf[bb][2], bf[bb][3]);
                }
            }
        }
    }
    __syncthreads();

    const int tg = lane >> 2, ti = lane & 3;
#pragma unroll
    for (int i = 0; i < 2; i++) {
#pragma unroll
        for (int j = 0; j < 8; j++) {
            const int gr0 = bm + wm * 32 + i * 16 + tg;
            const int gc  = bn + wn * 64 + j * 8 + ti * 2;
            const float b0 = bias[gc], b1 = bias[gc + 1];
#pragma unroll
            for (int hfl = 0; hfl < 2; hfl++) {
                const int gr = gr0 + hfl * 8;
                float v0 = acc[i][j][2*hfl + 0] + b0;
                float v1 = acc[i][j][2*hfl + 1] + b1;
                const size_t off = (size_t)gr * N + gc;
                if (EPI == 4) {
                    float2 rv = __half22float2(*(const __half2*)(resh + off));
                    v0 += rv.x; v1 += rv.y;
                }
                if (EPI == 2) {
                    float g0 = 0.5f * v0 * (1.0f + erff(v0 * 0.7071067811865476f));
                    float g1 = 0.5f * v1 * (1.0f + erff(v1 * 0.7071067811865476f));
                    v0 = g0 * g0; v1 = g1 * g1;
                }
                *(__half2*)(Ch + off) = __floats2half2_rn(v0, v1);
            }
        }
    }
}

// ------------------ fp32 -> fp16 convert (x) --------------------------------
__global__ void cvt_h(const float* __restrict__ in, __half* __restrict__ out, int n4)
{
    const int i = blockIdx.x * 256 + threadIdx.x;
    if (i >= n4) return;
    float4 v = ((const float4*)in)[i];
    ((__half2*)out)[2 * i]     = __floats2half2_rn(v.x, v.y);
    ((__half2*)out)[2 * i + 1] = __floats2half2_rn(v.z, v.w);
}

// --------- all 6 weight converts in one launch (flat float4 index) ----------
__global__ void cvt_weights(const float* __restrict__ wq, const float* __restrict__ wk,
                            const float* __restrict__ wv, const float* __restrict__ wo,
                            const float* __restrict__ w1, const float* __restrict__ w2,
                            __half* __restrict__ wqkvh, __half* __restrict__ woh,
                            __half* __restrict__ w1h, __half* __restrict__ w2h)
{
    const int i = blockIdx.x * 256 + threadIdx.x;   // float4 index, < 524288
    const float* src;
    __half* dst;
    int li;
    if (i < 196608) {
        li = i & 65535;
        src = (i < 65536) ? wq : (i < 131072) ? wk : wv;
        dst = wqkvh + (size_t)(i >> 16) * (Dn * Dn);
    } else if (i < 262144) { li = i - 196608; src = wo; dst = woh; }
    else if (i < 393216)   { li = i - 262144; src = w1; dst = w1h; }
    else                   { li = i - 393216; src = w2; dst = w2h; }
    float4 v = ((const float4*)src)[li];
    ((__half2*)dst)[2 * li]     = __floats2half2_rn(v.x, v.y);
    ((__half2*)dst)[2 * li + 1] = __floats2half2_rn(v.z, v.w);
}

// ------------------ pack 3 bias vectors into one ----------------------------
__global__ void pack3(const float* __restrict__ a, const float* __restrict__ b,
                      const float* __restrict__ c, float* __restrict__ o)
{
    const int i = blockIdx.x * 256 + threadIdx.x;
    if (i < Dn)            o[i] = a[i];
    else if (i < 2 * Dn)   o[i] = b[i - Dn];
    else if (i < 3 * Dn)   o[i] = c[i - 2 * Dn];
}

// ------------- conv(q,k,v) + elu+1(q,k) + partial KV (HMMA) / Ksum ---------
#define CPITCH 144
__global__ __launch_bounds__(256) void conv_pre(
    const __half* __restrict__ qkv,
    const float* __restrict__ qcw, const float* __restrict__ qcb,
    const float* __restrict__ kcw, const float* __restrict__ kcb,
    const float* __restrict__ vcw, const float* __restrict__ vcb)
{
    const int c = blockIdx.x, h = blockIdx.y, b = blockIdx.z;
    const int t  = threadIdx.x;
    const int p  = t & 31;
    const int rl = t >> 5;
    const int ch = 2 * p;
    const int w = t >> 5, lane = t & 31;
    const int mrow = lane >> 3, mr = lane & 7;
    const int dbase = (w & 3) * 16, ebase = (w >> 2) * 32;

    __shared__ __align__(16) char k2s[64 * CPITCH];
    __shared__ __align__(16) char v2s[64 * CPITCH];
    const uint32_t kbse = smem_u32(k2s);
    const uint32_t vbse = smem_u32(v2s);

    const float qw0a = qcw[ch*3+0], qw1a = qcw[ch*3+1], qw2a = qcw[ch*3+2], qba = qcb[ch];
    const float qw0b = qcw[ch*3+3], qw1b = qcw[ch*3+4], qw2b = qcw[ch*3+5], qbb = qcb[ch+1];
    const float kw0a = kcw[ch*3+0], kw1a = kcw[ch*3+1], kw2a = kcw[ch*3+2], kba = kcb[ch];
    const float kw0b = kcw[ch*3+3], kw1b = kcw[ch*3+4], kw2b = kcw[ch*3+5], kbb = kcb[ch+1];
    const float vw0a = vcw[ch*3+0], vw1a = vcw[ch*3+1], vw2a = vcw[ch*3+2], vba = vcb[ch];
    const float vw0b = vcw[ch*3+3], vw1b = vcw[ch*3+4], vw2b = vcw[ch*3+5], vbb = vcb[ch+1];

    float accm[4][4];
#pragma unroll
    for (int i = 0; i < 4; i++)
#pragma unroll
        for (int j = 0; j < 4; j++) accm[i][j] = 0.f;
    float ksacc = 0.f;

    for (int sub = 0; sub < 4; sub++) {
        __syncthreads();
        const int s0 = c * CHROWS + sub * 64 + rl * 8;
        const size_t qb0  = ((size_t)(b * Sn + s0)) * D3 + h * DKn + ch;
        const size_t q2b0 = ((size_t)(b * Sn + s0)) * Dn + h * DKn + ch;
        float2 qm1 = {0.f,0.f}, qm2 = {0.f,0.f};
        float2 km1 = {0.f,0.f}, km2 = {0.f,0.f};
        float2 vm1 = {0.f,0.f}, vm2 = {0.f,0.f};
        if (s0 >= 1) {
            qm1 = __half22float2(*(const __half2*)(qkv + qb0 - D3));
            km1 = __half22float2(*(const __half2*)(qkv + qb0 - D3 + Dn));
            vm1 = __half22float2(*(const __half2*)(qkv + qb0 - D3 + 2 * Dn));
        }
        if (s0 >= 2) {
            qm2 = __half22float2(*(const __half2*)(qkv + qb0 - 2 * D3));
            km2 = __half22float2(*(const __half2*)(qkv + qb0 - 2 * D3 + Dn));
            vm2 = __half22float2(*(const __half2*)(qkv + qb0 - 2 * D3 + 2 * Dn));
        }
#pragma unroll
        for (int i = 0; i < 8; i++) {
            const int r = rl * 8 + i;
            const size_t base = qb0 + (size_t)i * D3;

            float2 q0 = __half22float2(*(const __half2*)(qkv + base));
            float qcx = qw0a*qm2.x + qw1a*qm1.x + qw2a*q0.x + qba;
            float qcy = qw0b*qm2.y + qw1b*qm1.y + qw2b*q0.y + qbb;
            qcx = qcx > 0.f ? qcx + 1.f : __expf(qcx);
            qcy = qcy > 0.f ? qcy + 1.f : __expf(qcy);
            *(__half2*)(g_q2h + q2b0 + (size_t)i * Dn) = __floats2half2_rn(qcx, qcy);
            qm2 = qm1; qm1 = q0;

            float2 k0 = __half22float2(*(const __half2*)(qkv + base + Dn));
            float kcx = kw0a*km2.x + kw1a*km1.x + kw2a*k0.x + kba;
            float kcy = kw0b*km2.y + kw1b*km1.y + kw2b*k0.y + kbb;
            kcx = kcx > 0.f ? kcx + 1.f : __expf(kcx);
            kcy = kcy > 0.f ? kcy + 1.f : __expf(kcy);
            *(__half2*)(k2s + r * CPITCH + ch * 2) = __floats2half2_rn(kcx, kcy);
            km2 = km1; km1 = k0;

            float2 v0 = __half22float2(*(const __half2*)(qkv + base + 2 * Dn));
            float vcx = vw0a*vm2.x + vw1a*vm1.x + vw2a*v0.x + vba;
            float vcy = vw0b*vm2.y + vw1b*vm1.y + vw2b*v0.y + vbb;
            *(__half2*)(v2s + r * CPITCH + ch * 2) = __floats2half2_rn(vcx, vcy);
            vm2 = vm1; vm1 = v0;
        }
        __syncthreads();
        if (t < 64) {
#pragma unroll 8
            for (int r = 0; r < 64; r++)
                ksacc += __half2float(*(const __half*)(k2s + r * CPITCH + t * 2));
        }
#pragma unroll
        for (int ksb = 0; ksb < 4; ksb++) {
            uint32_t a[4];
            ldm4t(a, kbse + (ksb * 16 + (mrow >> 1) * 8 + mr) * CPITCH
                      + dbase * 2 + (mrow & 1) * 16);
#pragma unroll
            for (int jb = 0; jb < 2; jb++) {
                uint32_t t4[4];
                ldm4t(t4, vbse + (ksb * 16 + (mrow & 1) * 8 + mr) * CPITCH
                          + (ebase + jb * 16) * 2 + (mrow >> 1) * 16);
                mma16816(accm[2*jb],     a, t4[0], t4[1]);
                mma16816(accm[2*jb + 1], a, t4[2], t4[3]);
            }
        }
    }

    const int bh = b * Hn + h;
    const size_t kvbase = ((size_t)bh * NCH + c) * (DKn * DKn);
    const int tg = lane >> 2, ti = lane & 3;
#pragma unroll
    for (int jn = 0; jn < 4; jn++) {
#pragma unroll
        for (int hfl = 0; hfl < 2; hfl++) {
            const int d = dbase + hfl * 8 + tg;
            const int e = ebase + jn * 8 + ti * 2;
            g_kvp[kvbase + (size_t)d * DKn + e]     = accm[jn][2*hfl];
            g_kvp[kvbase + (size_t)d * DKn + e + 1] = accm[jn][2*hfl + 1];
        }
    }
    if (t < 64)
        g_ksp[((size_t)bh * NCH + c) * DKn + t] = ksacc;
}

// ---- reduce partial KV (-> fp16 transposed) / Ksum; grid (64, 4) ----------
__global__ void kv_reduce()
{
    const int bh = blockIdx.x, q = blockIdx.y, t = threadIdx.x;
    const int idx = q * 1024 + t * 4;
#pragma unroll
    for (int u = 0; u < 4; u++) {
        const int id = idx + u;
        float s = 0.f;
#pragma unroll
        for (int c = 0; c < NCH; c++)
            s += g_kvp[((size_t)bh * NCH + c) * (DKn * DKn) + id];
        const int d = id >> 6, e = id & 63;
        g_kvhT[(size_t)bh * (DKn * DKn) + e * DKn + d] = __float2half_rn(s);
    }
    if (q == 0 && t < DKn) {
        float s = 0.f;
#pragma unroll
        for (int c = 0; c < NCH; c++)
            s += g_ksp[((size_t)bh * NCH + c) * DKn + t];
        g_ks[(size_t)bh * DKn + t] = s;
    }
}

// ---- attn apply via HMMA: Vn = (Q @ KV) / (Q.(Ksum+eps)); 128 rows/block --
#define APITCH 144
__global__ __launch_bounds__(128) void attn_apply()
{
    const int st = blockIdx.x, h = blockIdx.y, b = blockIdx.z;
    const int t = threadIdx.x;
    const int bh = b * Hn + h;
    const int w = t >> 5, lane = t & 31;
    const int mrow = lane >> 3, mr = lane & 7;

    __shared__ __align__(16) char qsmem[64 * APITCH];
    __shared__ __align__(16) char ksmem[64 * APITCH];
    __shared__ float kss[64];
    __shared__ float zinv[64];

    const uint32_t qb = smem_u32(qsmem);
    const uint32_t kb = smem_u32(ksmem);

    for (int idx = t; idx < 1024; idx += 128) {
        const int r = idx >> 4, c4 = idx & 15;
        *(uint2*)(ksmem + r * APITCH + c4 * 8) =
            *(const uint2*)(g_kvhT + (size_t)bh * (DKn * DKn) + r * DKn + c4 * 4);
    }
    if (t < DKn) kss[t] = g_ks[(size_t)bh * DKn + t] + EPSA;

    for (int tile = 0; tile < 2; tile++) {
        const int row0 = st * 128 + tile * 64;
        __syncthreads();
        for (int idx = t; idx < 1024; idx += 128) {
            const int r = idx >> 4, c4 = idx & 15;
            *(uint2*)(qsmem + r * APITCH + c4 * 8) =
                *(const uint2*)(g_q2h + ((size_t)(b * Sn + row0 + r)) * Dn
                                + h * DKn + c4 * 4);
        }
        __syncthreads();

        {
            const int s = t >> 1, part = t & 1;
            float z = 0.f;
            const __half2* rp = (const __half2*)(qsmem + s * APITCH + part * 64);
#pragma unroll
            for (int d = 0; d < 16; d++) {
                float2 qv = __half22float2(rp[d]);
                z += qv.x * kss[part * 32 + 2 * d] + qv.y * kss[part * 32 + 2 * d + 1];
            }
            z += __shfl_xor_sync(0xffffffffu, z, 1);
            if (part == 0) zinv[s] = 1.0f / z;
        }

        float acc[8][4];
#pragma unroll
        for (int j = 0; j < 8; j++)
#pragma unroll
            for (int q = 0; q < 4; q++) acc[j][q] = 0.f;

#pragma unroll
        for (int ks = 0; ks < 4; ks++) {
            uint32_t ah[4];
            const int rowA = w * 16 + (mrow & 1) * 8 + mr;
            ldm4(ah, qb + rowA * APITCH + ks * 32 + (mrow >> 1) * 16);
#pragma unroll
            for (int jp = 0; jp < 4; jp++) {
                const int rowB = jp * 16 + (mrow >> 1) * 8 + mr;
                uint32_t t0[4];
                ldm4(t0, kb + rowB * APITCH + ks * 32 + (mrow & 1) * 16);
                mma16816(acc[2*jp],     ah, t0[0], t0[1]);
                mma16816(acc[2*jp + 1], ah, t0[2], t0[3]);
            }
        }
        __syncthreads();

        const int tg = lane >> 2, ti = lane & 3;
#pragma unroll
        for (int j = 0; j < 8; j++) {
            const int col = j * 8 + ti * 2;
#pragma unroll
            for (int hfl = 0; hfl < 2; hfl++) {
                const int row = w * 16 + hfl * 8 + tg;
                const float zi = zinv[row];
                const size_t off = ((size_t)(b * Sn + row0 + row)) * Dn
                                   + h * DKn + col;
                *(__half2*)(g_ath + off) =
                    __floats2half2_rn(zi * acc[j][2*hfl], zi * acc[j][2*hfl + 1]);
            }
        }
    }
}

// -------------------- LayerNorm (D=512), warp per row, fp16 in -------------
template<bool OUTF32>
__global__ __launch_bounds__(256) void ln_kernel(
    const __half* __restrict__ in, const float* __restrict__ gw,
    const float* __restrict__ bw, float* __restrict__ out,
    __half* __restrict__ oh)
{
    const int warp = threadIdx.x >> 5, lane = threadIdx.x & 31;
    const int row = blockIdx.x * 8 + warp;
    const uint4* rp = (const uint4*)(in + (size_t)row * Dn);

    float vals[16];
    float s1 = 0.f, s2 = 0.f;
#pragma unroll
    for (int i = 0; i < 2; i++) {
        uint4 raw = rp[lane + i * 32];
        const uint32_t u[4] = {raw.x, raw.y, raw.z, raw.w};
#pragma unroll
        for (int k = 0; k < 4; k++) {
            float2 f = __half22float2(*(const __half2*)&u[k]);
            vals[i * 8 + 2 * k]     = f.x;
            vals[i * 8 + 2 * k + 1] = f.y;
            s1 += f.x + f.y;
            s2 += f.x * f.x + f.y * f.y;
        }
    }
#pragma unroll
    for (int o = 16; o > 0; o >>= 1) {
        s1 += __shfl_xor_sync(0xffffffffu, s1, o);
        s2 += __shfl_xor_sync(0xffffffffu, s2, o);
    }
    const float m = s1 * (1.0f / Dn);
    const float rr = rsqrtf(s2 * (1.0f / Dn) - m * m + LNEPS);

#pragma unroll
    for (int i = 0; i < 2; i++) {
        const int c0 = (lane + i * 32) * 8;
        float o8[8];
#pragma unroll
        for (int k = 0; k < 2; k++) {
            const float4 g4 = *(const float4*)(gw + c0 + k * 4);
            const float4 b4 = *(const float4*)(bw + c0 + k * 4);
            o8[k*4+0] = (vals[i*8 + k*4 + 0] - m) * rr * g4.x + b4.x;
            o8[k*4+1] = (vals[i*8 + k*4 + 1] - m) * rr * g4.y + b4.y;
            o8[k*4+2] = (vals[i*8 + k*4 + 2] - m) * rr * g4.z + b4.z;
            o8[k*4+3] = (vals[i*8 + k*4 + 3] - m) * rr * g4.w + b4.w;
        }
        if (OUTF32) {
#pragma unroll
            for (int k = 0; k < 2; k++) {
                float4 o4; o4.x = o8[k*4]; o4.y = o8[k*4+1];
                o4.z = o8[k*4+2]; o4.w = o8[k*4+3];
                *(float4*)(out + (size_t)row * Dn + c0 + k * 4) = o4;
            }
        } else {
            uint4 packed;
            __half2 p0 = __floats2half2_rn(o8[0], o8[1]);
            __half2 p1 = __floats2half2_rn(o8[2], o8[3]);
            __half2 p2 = __floats2half2_rn(o8[4], o8[5]);
            __half2 p3 = __floats2half2_rn(o8[6], o8[7]);
            packed.x = *(uint32_t*)&p0; packed.y = *(uint32_t*)&p1;
            packed.z = *(uint32_t*)&p2; packed.w = *(uint32_t*)&p3;
            *(uint4*)(oh + (size_t)row * Dn + c0) = packed;
        }
    }
}

// ------------------------------- launch ------------------------------------
extern "C" void kernel_launch(void* const* d_in, const int* in_sizes, int n_in,
                              void* d_out, int out_size)
{
    const float* x    = (const float*)d_in[0];
    const float* wq   = (const float*)d_in[1];
    const float* bq   = (const float*)d_in[2];
    const float* wk   = (const float*)d_in[3];
    const float* bk   = (const float*)d_in[4];
    const float* wv   = (const float*)d_in[5];
    const float* bv   = (const float*)d_in[6];
    const float* wo   = (const float*)d_in[7];
    const float* bo   = (const float*)d_in[8];
    const float* qcw  = (const float*)d_in[9];
    const float* qcb  = (const float*)d_in[10];
    const float* kcw  = (const float*)d_in[11];
    const float* kcb  = (const float*)d_in[12];
    const float* vcw  = (const float*)d_in[13];
    const float* vcb  = (const float*)d_in[14];
    const float* w1   = (const float*)d_in[15];
    const float* b1   = (const float*)d_in[16];
    const float* w2   = (const float*)d_in[17];
    const float* b2   = (const float*)d_in[18];
    const float* ln1g = (const float*)d_in[19];
    const float* ln1b = (const float*)d_in[20];
    const float* ln2g = (const float*)d_in[21];
    const float* ln2b = (const float*)d_in[22];
    float* out = (float*)d_out;

    float* pbqkv;
    cudaGetSymbolAddress((void**)&pbqkv, g_bqkv);

    __half *pqkvh, *pxh, *path, *pyh, *px1h, *phh, *py2h;
    __half *pwqkvh, *pwoh, *pw1h, *pw2h;
    cudaGetSymbolAddress((void**)&pqkvh,  g_qkvh);
    cudaGetSymbolAddress((void**)&pxh,    g_xh);
    cudaGetSymbolAddress((void**)&path,   g_ath);
    cudaGetSymbolAddress((void**)&pyh,    g_yh);
    cudaGetSymbolAddress((void**)&px1h,   g_x1h);
    cudaGetSymbolAddress((void**)&phh,    g_hh);
    cudaGetSymbolAddress((void**)&py2h,   g_y2h);
    cudaGetSymbolAddress((void**)&pwqkvh, g_wqkvh);
    cudaGetSymbolAddress((void**)&pwoh,   g_woh);
    cudaGetSymbolAddress((void**)&pw1h,   g_w1h);
    cudaGetSymbolAddress((void**)&pw2h,   g_w2h);

    cudaFuncSetAttribute(gemm_mma<2>, cudaFuncAttributeMaxDynamicSharedMemorySize, GSMEM);
    cudaFuncSetAttribute(gemm_mma<3>, cudaFuncAttributeMaxDynamicSharedMemorySize, GSMEM);
    cudaFuncSetAttribute(gemm_mma<4>, cudaFuncAttributeMaxDynamicSharedMemorySize, GSMEM);

    const dim3 gridQKV(D3 / 256, Mn / 128);   // (6, 256)
    const dim3 gridD(Dn / 256, Mn / 128);     // (2, 256)
    const dim3 gridF(DFFn / 256, Mn / 128);   // (4, 256)

    // elementwise prep
    cvt_h<<<(Mn * Dn / 4 + 255) / 256, 256>>>(x, pxh, Mn * Dn / 4);
    cvt_weights<<<2048, 256>>>(wq, wk, wv, wo, w1, w2,
                               pwqkvh, pwoh, pw1h, pw2h);
    pack3<<<(D3 + 255) / 256, 256>>>(bq, bk, bv, pbqkv);

    // merged QKV projection -> fp16
    gemm_mma<3><<<gridQKV, 512, GSMEM>>>(pxh, pwqkvh, pbqkv, nullptr,
                                         pqkvh, Mn, D3, Dn);

    // depthwise conv + elu+1 + partial KV (HMMA) / Ksum
    conv_pre<<<dim3(NCH, Hn, Bn), 256>>>(pqkvh, qcw, qcb, kcw, kcb, vcw, vcb);
    kv_reduce<<<dim3(Bn * Hn, 4), 256>>>();
    attn_apply<<<dim3(Sn / 128, Hn, Bn), 128>>>();

    // O-proj + residual(xh fp16) -> fp16 y; LN1 fp16->fp16
    gemm_mma<4><<<gridD, 512, GSMEM>>>(path, pwoh, bo, pxh, pyh, Mn, Dn, Dn);
    ln_kernel<false><<<Mn / 8, 256>>>(pyh, ln1g, ln1b, nullptr, px1h);

    // FFN1 gelu^2 -> fp16; FFN2 + residual(x1h fp16) -> fp16; LN2 -> fp32 out
    gemm_mma<2><<<gridF, 512, GSMEM>>>(px1h, pw1h, b1, nullptr, phh, Mn, DFFn, Dn);
    gemm_mma<4><<<gridD, 512, GSMEM>>>(phh, pw2h, b2, px1h, py2h, Mn, Dn, DFFn);
    ln_kernel<true><<<Mn / 8, 256>>>(py2h, ln2g, ln2b, out, nullptr);
}